// round 9
// baseline (speedup 1.0000x reference)
#include <cuda_runtime.h>
#include <cuda_fp16.h>

#define N_NODES 50000
#define N_EDGES 1600000
#define NATT    64
#define NHEAD   4

#define ATT_OFF   0
#define V_OFF     (N_EDGES * NHEAD)
#define PRODS_OFF (N_EDGES * NHEAD + N_NODES * NATT)

// Scratch (allocation-free). Q/K fp16 halves edge-gather BW.
__device__ __half g_Qh[N_NODES * NATT];
__device__ __half g_Kh[N_NODES * NATT];
__device__ float  g_denom[N_NODES * NHEAD];
// Transposed weights: g_Wt[m][col][k], m in {q,k,v}
__device__ float  g_Wt[3][NATT][NATT];

__device__ __forceinline__ float2 ffma2(float2 a, float2 b, float2 c) {
    unsigned long long ra = *reinterpret_cast<unsigned long long*>(&a);
    unsigned long long rb = *reinterpret_cast<unsigned long long*>(&b);
    unsigned long long rc = *reinterpret_cast<unsigned long long*>(&c);
    unsigned long long rd;
    asm("fma.rn.f32x2 %0, %1, %2, %3;" : "=l"(rd) : "l"(ra), "l"(rb), "l"(rc));
    return *reinterpret_cast<float2*>(&rd);
}

// ---------------------------------------------------------------------------
// K0: transpose W (k-major -> col-major) so proj can LDG.128 along k.
// ---------------------------------------------------------------------------
__global__ __launch_bounds__(256) void wt_kernel(
    const float* __restrict__ Wq, const float* __restrict__ Wk,
    const float* __restrict__ Wv)
{
    const int t = blockIdx.x * 256 + threadIdx.x;   // 48 blocks * 256 = 12288
    if (t >= 3 * NATT * NATT) return;
    const int m = t / (NATT * NATT);
    const int r = t % (NATT * NATT);
    const int col = r / NATT, k = r % NATT;
    const float* W = (m == 0) ? Wq : (m == 1) ? Wk : Wv;
    g_Wt[m][col][k] = W[k * NATT + col];
}

// ---------------------------------------------------------------------------
// K1: fused Q/K/V projection. 4 groups x 64 lanes; 8 nodes per group member.
//     W loaded via LDG.128 (4 k at a time) from transposed copy.
// ---------------------------------------------------------------------------
#define NPB 32

__global__ __launch_bounds__(256) void proj_kernel(
    const float* __restrict__ x,
    const float* __restrict__ bq, const float* __restrict__ bk,
    const float* __restrict__ bv,
    float* __restrict__ out)
{
    __shared__ float xs_t[NATT][36];   // [k][node_local]

    const int tid  = threadIdx.x;
    const int base = blockIdx.x * NPB;

    const int gt = blockIdx.x * 256 + tid;
    if (gt < N_NODES * NHEAD) g_denom[gt] = 0.0f;

    // transposed stage of x[base..base+31][0..63]
    {
        const int nl = tid >> 3;
        const int k0 = (tid & 7) * 8;
        const int node = base + nl;
        if (node < N_NODES) {
            const float4 a = *(const float4*)&x[node * NATT + k0];
            const float4 b = *(const float4*)&x[node * NATT + k0 + 4];
            xs_t[k0 + 0][nl] = a.x; xs_t[k0 + 1][nl] = a.y;
            xs_t[k0 + 2][nl] = a.z; xs_t[k0 + 3][nl] = a.w;
            xs_t[k0 + 4][nl] = b.x; xs_t[k0 + 5][nl] = b.y;
            xs_t[k0 + 6][nl] = b.z; xs_t[k0 + 7][nl] = b.w;
        }
    }
    __syncthreads();

    const int lane = tid & 63;
    const int g    = tid >> 6;
    const int gn   = g * 8;

    float2 aq[4], ak[4], av[4];
#pragma unroll
    for (int j = 0; j < 4; j++) {
        aq[j] = make_float2(0.f, 0.f);
        ak[j] = make_float2(0.f, 0.f);
        av[j] = make_float2(0.f, 0.f);
    }

    const float* __restrict__ wqr = &g_Wt[0][lane][0];
    const float* __restrict__ wkr = &g_Wt[1][lane][0];
    const float* __restrict__ wvr = &g_Wt[2][lane][0];

#pragma unroll 2
    for (int kc = 0; kc < NATT; kc += 4) {
        const float4 wq4 = *(const float4*)&wqr[kc];
        const float4 wk4 = *(const float4*)&wkr[kc];
        const float4 wv4 = *(const float4*)&wvr[kc];
        const float wqa[4] = { wq4.x, wq4.y, wq4.z, wq4.w };
        const float wka[4] = { wk4.x, wk4.y, wk4.z, wk4.w };
        const float wva[4] = { wv4.x, wv4.y, wv4.z, wv4.w };

#pragma unroll
        for (int kk = 0; kk < 4; kk++) {
            const int k = kc + kk;
            const float2 wq2 = make_float2(wqa[kk], wqa[kk]);
            const float2 wk2 = make_float2(wka[kk], wka[kk]);
            const float2 wv2 = make_float2(wva[kk], wva[kk]);

            const float4 xa = *(const float4*)&xs_t[k][gn];
            const float4 xb = *(const float4*)&xs_t[k][gn + 4];
            const float2 xp[4] = { make_float2(xa.x, xa.y), make_float2(xa.z, xa.w),
                                   make_float2(xb.x, xb.y), make_float2(xb.z, xb.w) };
#pragma unroll
            for (int j = 0; j < 4; j++) {
                aq[j] = ffma2(xp[j], wq2, aq[j]);
                ak[j] = ffma2(xp[j], wk2, ak[j]);
                av[j] = ffma2(xp[j], wv2, av[j]);
            }
        }
    }

    const float bqv = __ldg(&bq[lane]);
    const float bkv = __ldg(&bk[lane]);
    const float bvv = __ldg(&bv[lane]);
    const int d = lane & 15, h = lane >> 4;

#pragma unroll
    for (int j = 0; j < 4; j++) {
        const int n0 = base + gn + 2 * j;
        if (n0 < N_NODES) {
            g_Qh[n0 * NATT + lane] = __float2half((aq[j].x + bqv) * 0.25f);
            g_Kh[n0 * NATT + lane] = __float2half(ak[j].x + bkv);
            out[V_OFF + n0 * NATT + d * NHEAD + h] = av[j].x + bvv;
        }
        if (n0 + 1 < N_NODES) {
            g_Qh[(n0 + 1) * NATT + lane] = __float2half((aq[j].y + bqv) * 0.25f);
            g_Kh[(n0 + 1) * NATT + lane] = __float2half(ak[j].y + bkv);
            out[V_OFF + (n0 + 1) * NATT + d * NHEAD + h] = av[j].y + bvv;
        }
    }
}

// ---------------------------------------------------------------------------
// K2: per-(edge, head) dot product, prods + exp + segment-sum atomics.
// ---------------------------------------------------------------------------
__global__ __launch_bounds__(256) void edge_kernel(
    const int* __restrict__ edge,
    float* __restrict__ out)
{
    const int t = blockIdx.x * 256 + threadIdx.x;
    if (t >= N_EDGES * NHEAD) return;

    const int e = t >> 2;
    const int h = t & 3;
    const int s = __ldg(&edge[e]);
    const int v = __ldg(&edge[N_EDGES + e]);

    const float4* __restrict__ qp = (const float4*)(g_Qh + s * NATT + h * 16);
    const float4* __restrict__ kp = (const float4*)(g_Kh + v * NATT + h * 16);

    float2 acc2 = make_float2(0.f, 0.f);
#pragma unroll
    for (int i = 0; i < 2; i++) {
        float4 qv = qp[i];
        float4 kv = kp[i];
        const __half2* qh = (const __half2*)&qv;
        const __half2* kh = (const __half2*)&kv;
#pragma unroll
        for (int j = 0; j < 4; j++) {
            acc2 = ffma2(__half22float2(qh[j]), __half22float2(kh[j]), acc2);
        }
    }
    const float acc = acc2.x + acc2.y;

    out[PRODS_OFF + t] = acc;
    const float ex = __expf(acc);
    out[ATT_OFF + t] = ex;
    atomicAdd(&g_denom[s * NHEAD + h], ex);
}

// ---------------------------------------------------------------------------
// K3: normalize attention. One thread per EDGE: float4 att load/store,
//     single edge[e] load, float4 denom load (one 32B sector per edge).
// ---------------------------------------------------------------------------
__global__ __launch_bounds__(256) void norm_kernel(
    const int* __restrict__ edge,
    float* __restrict__ out)
{
    const int e = blockIdx.x * 256 + threadIdx.x;
    if (e >= N_EDGES) return;

    const int s = __ldg(&edge[e]);
    const float4 den = *(const float4*)&g_denom[s * NHEAD];
    float4 a = *(float4*)&out[ATT_OFF + e * NHEAD];

    a.x = __fdividef(a.x, den.x + 1e-16f);
    a.y = __fdividef(a.y, den.y + 1e-16f);
    a.z = __fdividef(a.z, den.z + 1e-16f);
    a.w = __fdividef(a.w, den.w + 1e-16f);

    *(float4*)&out[ATT_OFF + e * NHEAD] = a;
}

// ---------------------------------------------------------------------------
extern "C" void kernel_launch(void* const* d_in, const int* in_sizes, int n_in,
                              void* d_out, int out_size)
{
    const float* x    = (const float*)d_in[0];
    const int*   edge = (const int*)  d_in[1];
    const float* Wq   = (const float*)d_in[2];
    const float* bq   = (const float*)d_in[3];
    const float* Wk   = (const float*)d_in[4];
    const float* bk   = (const float*)d_in[5];
    const float* Wv   = (const float*)d_in[6];
    const float* bv   = (const float*)d_in[7];
    float* out = (float*)d_out;

    const int proj_blocks = (N_NODES + NPB - 1) / NPB;
    const int edge_blocks = (N_EDGES * NHEAD + 255) / 256;
    const int norm_blocks = (N_EDGES + 255) / 256;

    wt_kernel<<<48, 256>>>(Wq, Wk, Wv);
    proj_kernel<<<proj_blocks, 256>>>(x, bq, bk, bv, out);
    edge_kernel<<<edge_blocks, 256>>>(edge, out);
    norm_kernel<<<norm_blocks, 256>>>(edge, out);
}

// round 15
// speedup vs baseline: 1.0171x; 1.0171x over previous
#include <cuda_runtime.h>
#include <cuda_fp16.h>

#define N_NODES 50000
#define N_EDGES 1600000
#define NATT    64
#define NHEAD   4

#define ATT_OFF   0
#define V_OFF     (N_EDGES * NHEAD)
#define PRODS_OFF (N_EDGES * NHEAD + N_NODES * NATT)

// Scratch (allocation-free). Q/K fp16 halves edge-gather BW.
__device__ __half g_Qh[N_NODES * NATT];
__device__ __half g_Kh[N_NODES * NATT];
__device__ float  g_denom[N_NODES * NHEAD];
// Transposed weights: g_Wt[m][col][k], m in {q,k,v}
__device__ float  g_Wt[3][NATT][NATT];

__device__ __forceinline__ float2 ffma2(float2 a, float2 b, float2 c) {
    unsigned long long ra = *reinterpret_cast<unsigned long long*>(&a);
    unsigned long long rb = *reinterpret_cast<unsigned long long*>(&b);
    unsigned long long rc = *reinterpret_cast<unsigned long long*>(&c);
    unsigned long long rd;
    asm("fma.rn.f32x2 %0, %1, %2, %3;" : "=l"(rd) : "l"(ra), "l"(rb), "l"(rc));
    return *reinterpret_cast<float2*>(&rd);
}

// ---------------------------------------------------------------------------
// K0: transpose W (k-major -> col-major) so proj can LDG.128 along k.
// ---------------------------------------------------------------------------
__global__ __launch_bounds__(256) void wt_kernel(
    const float* __restrict__ Wq, const float* __restrict__ Wk,
    const float* __restrict__ Wv)
{
    const int t = blockIdx.x * 256 + threadIdx.x;   // 48 blocks * 256 = 12288
    if (t >= 3 * NATT * NATT) return;
    const int m = t / (NATT * NATT);
    const int r = t % (NATT * NATT);
    const int col = r / NATT, k = r % NATT;
    const float* W = (m == 0) ? Wq : (m == 1) ? Wk : Wv;
    g_Wt[m][col][k] = W[k * NATT + col];
}

// ---------------------------------------------------------------------------
// K1: fused Q/K/V projection. 4 groups x 64 lanes; 8 nodes per group member.
//     W via LDG.128 from transposed copy. Chunk loop kept at unroll 1 to
//     bound live registers (spill-free; R9's unroll-2 variant spilled).
// ---------------------------------------------------------------------------
#define NPB 32

__global__ __launch_bounds__(256) void proj_kernel(
    const float* __restrict__ x,
    const float* __restrict__ bq, const float* __restrict__ bk,
    const float* __restrict__ bv,
    float* __restrict__ out)
{
    __shared__ float xs_t[NATT][36];   // [k][node_local]

    const int tid  = threadIdx.x;
    const int base = blockIdx.x * NPB;

    const int gt = blockIdx.x * 256 + tid;
    if (gt < N_NODES * NHEAD) g_denom[gt] = 0.0f;

    // transposed stage of x[base..base+31][0..63]
    {
        const int nl = tid >> 3;
        const int k0 = (tid & 7) * 8;
        const int node = base + nl;
        if (node < N_NODES) {
            const float4 a = *(const float4*)&x[node * NATT + k0];
            const float4 b = *(const float4*)&x[node * NATT + k0 + 4];
            xs_t[k0 + 0][nl] = a.x; xs_t[k0 + 1][nl] = a.y;
            xs_t[k0 + 2][nl] = a.z; xs_t[k0 + 3][nl] = a.w;
            xs_t[k0 + 4][nl] = b.x; xs_t[k0 + 5][nl] = b.y;
            xs_t[k0 + 6][nl] = b.z; xs_t[k0 + 7][nl] = b.w;
        }
    }
    __syncthreads();

    const int lane = tid & 63;
    const int g    = tid >> 6;
    const int gn   = g * 8;

    float2 aq[4], ak[4], av[4];
#pragma unroll
    for (int j = 0; j < 4; j++) {
        aq[j] = make_float2(0.f, 0.f);
        ak[j] = make_float2(0.f, 0.f);
        av[j] = make_float2(0.f, 0.f);
    }

    const float* __restrict__ wqr = &g_Wt[0][lane][0];
    const float* __restrict__ wkr = &g_Wt[1][lane][0];
    const float* __restrict__ wvr = &g_Wt[2][lane][0];

#pragma unroll 1
    for (int kc = 0; kc < NATT; kc += 4) {
        const float4 wq4 = *(const float4*)&wqr[kc];
        const float4 wk4 = *(const float4*)&wkr[kc];
        const float4 wv4 = *(const float4*)&wvr[kc];
        const float wqa[4] = { wq4.x, wq4.y, wq4.z, wq4.w };
        const float wka[4] = { wk4.x, wk4.y, wk4.z, wk4.w };
        const float wva[4] = { wv4.x, wv4.y, wv4.z, wv4.w };

#pragma unroll
        for (int kk = 0; kk < 4; kk++) {
            const int k = kc + kk;
            const float2 wq2 = make_float2(wqa[kk], wqa[kk]);
            const float2 wk2 = make_float2(wka[kk], wka[kk]);
            const float2 wv2 = make_float2(wva[kk], wva[kk]);

            const float4 xa = *(const float4*)&xs_t[k][gn];
            const float4 xb = *(const float4*)&xs_t[k][gn + 4];
            const float2 xp[4] = { make_float2(xa.x, xa.y), make_float2(xa.z, xa.w),
                                   make_float2(xb.x, xb.y), make_float2(xb.z, xb.w) };
#pragma unroll
            for (int j = 0; j < 4; j++) {
                aq[j] = ffma2(xp[j], wq2, aq[j]);
                ak[j] = ffma2(xp[j], wk2, ak[j]);
                av[j] = ffma2(xp[j], wv2, av[j]);
            }
        }
    }

    const float bqv = __ldg(&bq[lane]);
    const float bkv = __ldg(&bk[lane]);
    const float bvv = __ldg(&bv[lane]);
    const int d = lane & 15, h = lane >> 4;

#pragma unroll
    for (int j = 0; j < 4; j++) {
        const int n0 = base + gn + 2 * j;
        if (n0 < N_NODES) {
            g_Qh[n0 * NATT + lane] = __float2half((aq[j].x + bqv) * 0.25f);
            g_Kh[n0 * NATT + lane] = __float2half(ak[j].x + bkv);
            out[V_OFF + n0 * NATT + d * NHEAD + h] = av[j].x + bvv;
        }
        if (n0 + 1 < N_NODES) {
            g_Qh[(n0 + 1) * NATT + lane] = __float2half((aq[j].y + bqv) * 0.25f);
            g_Kh[(n0 + 1) * NATT + lane] = __float2half(ak[j].y + bkv);
            out[V_OFF + (n0 + 1) * NATT + d * NHEAD + h] = av[j].y + bvv;
        }
    }
}

// ---------------------------------------------------------------------------
// K2: per-(edge, head) dot product, prods + exp + segment-sum atomics.
// ---------------------------------------------------------------------------
__global__ __launch_bounds__(256) void edge_kernel(
    const int* __restrict__ edge,
    float* __restrict__ out)
{
    const int t = blockIdx.x * 256 + threadIdx.x;
    if (t >= N_EDGES * NHEAD) return;

    const int e = t >> 2;
    const int h = t & 3;
    const int s = __ldg(&edge[e]);
    const int v = __ldg(&edge[N_EDGES + e]);

    const float4* __restrict__ qp = (const float4*)(g_Qh + s * NATT + h * 16);
    const float4* __restrict__ kp = (const float4*)(g_Kh + v * NATT + h * 16);

    float2 acc2 = make_float2(0.f, 0.f);
#pragma unroll
    for (int i = 0; i < 2; i++) {
        float4 qv = qp[i];
        float4 kv = kp[i];
        const __half2* qh = (const __half2*)&qv;
        const __half2* kh = (const __half2*)&kv;
#pragma unroll
        for (int j = 0; j < 4; j++) {
            acc2 = ffma2(__half22float2(qh[j]), __half22float2(kh[j]), acc2);
        }
    }
    const float acc = acc2.x + acc2.y;

    out[PRODS_OFF + t] = acc;
    const float ex = __expf(acc);
    out[ATT_OFF + t] = ex;
    atomicAdd(&g_denom[s * NHEAD + h], ex);
}

// ---------------------------------------------------------------------------
// K3: normalize attention. One thread per EDGE: float4 att load/store,
//     single edge[e] load, float4 denom load (one 32B sector per edge).
// ---------------------------------------------------------------------------
__global__ __launch_bounds__(256) void norm_kernel(
    const int* __restrict__ edge,
    float* __restrict__ out)
{
    const int e = blockIdx.x * 256 + threadIdx.x;
    if (e >= N_EDGES) return;

    const int s = __ldg(&edge[e]);
    const float4 den = *(const float4*)&g_denom[s * NHEAD];
    float4 a = *(float4*)&out[ATT_OFF + e * NHEAD];

    a.x = __fdividef(a.x, den.x + 1e-16f);
    a.y = __fdividef(a.y, den.y + 1e-16f);
    a.z = __fdividef(a.z, den.z + 1e-16f);
    a.w = __fdividef(a.w, den.w + 1e-16f);

    *(float4*)&out[ATT_OFF + e * NHEAD] = a;
}

// ---------------------------------------------------------------------------
extern "C" void kernel_launch(void* const* d_in, const int* in_sizes, int n_in,
                              void* d_out, int out_size)
{
    const float* x    = (const float*)d_in[0];
    const int*   edge = (const int*)  d_in[1];
    const float* Wq   = (const float*)d_in[2];
    const float* bq   = (const float*)d_in[3];
    const float* Wk   = (const float*)d_in[4];
    const float* bk   = (const float*)d_in[5];
    const float* Wv   = (const float*)d_in[6];
    const float* bv   = (const float*)d_in[7];
    float* out = (float*)d_out;

    const int proj_blocks = (N_NODES + NPB - 1) / NPB;
    const int edge_blocks = (N_EDGES * NHEAD + 255) / 256;
    const int norm_blocks = (N_EDGES + 255) / 256;

    wt_kernel<<<48, 256>>>(Wq, Wk, Wv);
    proj_kernel<<<proj_blocks, 256>>>(x, bq, bk, bv, out);
    edge_kernel<<<edge_blocks, 256>>>(edge, out);
    norm_kernel<<<norm_blocks, 256>>>(edge, out);
}